// round 15
// baseline (speedup 1.0000x reference)
#include <cuda_runtime.h>

#define NB 4
#define NC 200
#define NG 32
#define NN 32256
#define CH 128                    // anchors per block
#define NBX (NN / CH)             // 252
#define TOTAL_BLOCKS (NB * NBX)   // 1008 -> single wave at 7 blocks/SM
#define LOG2E 1.4426950408889634f
#define LN2   0.69314718055994531f

__device__ double g_acc[3];
__device__ unsigned g_cnt;
__device__ unsigned g_done;

__device__ __forceinline__ float f_ex2(float x){ float r; asm("ex2.approx.ftz.f32 %0,%1;" : "=f"(r) : "f"(x)); return r; }
__device__ __forceinline__ float f_lg2(float x){ float r; asm("lg2.approx.ftz.f32 %0,%1;" : "=f"(r) : "f"(x)); return r; }
__device__ __forceinline__ float f_rcp(float x){ float r; asm("rcp.approx.ftz.f32 %0,%1;" : "=f"(r) : "f"(x)); return r; }

// 2-MUFU core (warps 0-3): ex2 + lg2 on MUFU, rcp via magic+Halley.
__device__ __forceinline__ float g0_2m(float x) {
    float t = x * LOG2E;
    float u = f_ex2(t);                    // MUFU
    float s = 1.f + u;
    float l = f_lg2(s);                    // MUFU
    float r0 = __int_as_float(0x7EF311C3 - __float_as_int(s));
    float h  = fmaf(-s, r0, 1.f);
    float r  = fmaf(r0, fmaf(h, h, h), r0);
    float w = u * r;
    return l * w * w;
}

// 1-MUFU core (warps 4-7): only ex2(-|t|) on MUFU.
//   softplus identity: lg2(1+e^x) = lg2(1+e^-|x|) + max(t,0),  t = x*log2e
//   sa = 1+e^-|x| in (1,2]: lg2(sa) = lg2(1.5) + log2e*wv*P(wv),
//     wv = (ua-0.5)/1.5 in [-1/3,1/3], P = deg-7 Taylor of ln(1+wv)/wv  (err<=8e-6)
//   sigma(x) = (t>=0 ? 1 : ua) / sa;  1/sa via magic seed + Halley.
__device__ __forceinline__ float g0_p1(float x) {
    float t  = x * LOG2E;
    float tp = fmaxf(t, 0.f);
    float tn = fminf(t, -t);               // -|t|
    float ua = f_ex2(tn);                  // MUFU (the only one)
    float sa = 1.f + ua;
    float r0 = __int_as_float(0x7EF311C3 - __float_as_int(sa));
    float h  = fmaf(-sa, r0, 1.f);
    float r  = fmaf(r0, fmaf(h, h, h), r0);
    float wv = fmaf(ua, 0.66666667f, -0.33333333f);
    float p  = -0.125f;
    p = fmaf(p, wv,  0.14285714f);
    p = fmaf(p, wv, -0.16666667f);
    p = fmaf(p, wv,  0.2f);
    p = fmaf(p, wv, -0.25f);
    p = fmaf(p, wv,  0.33333333f);
    p = fmaf(p, wv, -0.5f);
    p = fmaf(p, wv,  1.f);
    float la = fmaf(p, wv * LOG2E, 0.58496250f);   // lg2(sa)
    float lt = la + tp;                            // lg2(1+e^x)
    float um = (t >= 0.f) ? 1.f : ua;
    float w  = um * r;                             // sigmoid(x)
    return lt * w * w;
}

__global__ void __launch_bounds__(256, 7)
loss_fused(const float* __restrict__ logits,        // [B,N,C]
           const float* __restrict__ psegs,         // [B,N,3]
           const float* __restrict__ grids,         // [B,N]
           const float* __restrict__ fps,           // [B]
           const float* __restrict__ gts,           // [B,G,2]
           const int*   __restrict__ glab,          // [B,G]
           const unsigned char* __restrict__ mask,  // [B,N]
           float* __restrict__ out)                 // [3]
{
    __shared__ unsigned s_tgt[CH * 8];   // 224-bit class-target mask per anchor
    __shared__ float    s_gv[CH], s_p1[CH], s_p2[CH], s_vv[CH];
    __shared__ float    s_red[3 * 8];
    __shared__ int      s_redc[8];

    const int tid  = threadIdx.x;
    const int lane = tid & 31;
    const int warp = tid >> 5;
    const int b    = blockIdx.y;
    const int n0   = blockIdx.x * CH;

    #pragma unroll
    for (int k = 0; k < 4; ++k) s_tgt[tid + k * 256] = 0u;
    if (tid < CH) {
        long long bn = (long long)b * NN + n0 + tid;
        s_gv[tid] = grids[bn];
        s_p1[tid] = psegs[bn * 3 + 1];
        s_p2[tid] = psegs[bn * 3 + 2];
        s_vv[tid] = mask[bn] ? 0.f : 1.f;
    }
    __syncthreads();

    // ---------------- Phase A: matching + seg/IoU + target masks ----------
    float2 seg  = ((const float2*)gts)[b * NG + lane];
    float s_g   = seg.x, e_g = seg.y;
    float len_g = e_g - s_g;
    int   lbl   = glab[b * NG + lane];
    float Cm    = 3.0f * fps[b] * 1.41421356237309515f;  // 3*fps*sqrt(2)

    int lvl = (n0 >= 16384) + (n0 >= 24576) + (n0 >= 28672) + (n0 >= 30720) + (n0 >= 31744);
    float lo = (lvl == 0) ? 0.f : Cm * (float)(1 << (lvl - 1));
    float hi = (lvl == 5) ? __int_as_float(0x7f800000) : Cm * (float)(1 << lvl);
    bool inb = (len_g >= lo) && (len_g < hi);

    float ce_acc = 0.f, seg_acc = 0.f, iou_acc = 0.f;
    int cnt = 0;

    #pragma unroll 4
    for (int i = 0; i < CH / 8; ++i) {   // 16 anchors per warp
        int a = warp * (CH / 8) + i;
        float gv = s_gv[a];
        bool pos = inb && (gv > s_g) && (gv < e_g);
        if (pos) {
            cnt++;
            float ps1 = s_p1[a], ps2 = s_p2[a];
            float d1 = ps1 - __logf(gv - s_g);
            float d2 = ps2 - __logf(e_g - gv);
            float a1 = fabsf(d1), a2 = fabsf(d2);
            seg_acc += (a1 < 1.f ? 0.5f * d1 * d1 : a1 - 0.5f)
                     + (a2 < 1.f ? 0.5f * d2 * d2 : a2 - 0.5f);
            float pls = gv - __expf(ps1);
            float ple = gv + __expf(ps2);
            float inter = fmaxf(fminf(ple, e_g) - fmaxf(pls, s_g), 0.f);
            float uni   = (ple - pls) + len_g - inter;
            iou_acc += 1.f - __fdividef(inter, uni);
            atomicOr(&s_tgt[a * 8 + (lbl >> 5)], 1u << (lbl & 31));
        }
    }
    // no barrier: phase B reads no phase-A shared state

    // ---------------- Phase B: SMSP-paired warp-specialized stream ---------
    // wid%4 selects the SMSP, so pairs (0,4),(1,5),(2,6),(3,7) co-reside.
    // Warps 0-3: 2-MUFU core on quads [0,3200)  (anchors 0..63)
    // Warps 4-7: 1-MUFU core on quads [3200,6400) (anchors 64..127)
    // -> every SMSP sees one MUFU-heavy and one FMA-heavy warp: pipe balance.
    const float4* basep = (const float4*)(logits + ((size_t)b * NN + n0) * NC);
    float c0 = 0.f, c1 = 0.f, c2 = 0.f, c3 = 0.f;
    if (warp < 4) {
        int g = warp * 32 + lane;
        float4 v = basep[g];
        #pragma unroll
        for (int k = 0; k < 25; ++k) {
            float4 vn;
            if (k + 1 < 25) vn = basep[g + (k + 1) * 128];
            c0 += g0_2m(v.x);
            c1 += g0_2m(v.y);
            c2 += g0_2m(v.z);
            c3 += g0_2m(v.w);
            if (k + 1 < 25) v = vn;
        }
    } else {
        int g = 3200 + (warp - 4) * 32 + lane;
        float4 v = basep[g];
        #pragma unroll
        for (int k = 0; k < 25; ++k) {
            float4 vn;
            if (k + 1 < 25) vn = basep[g + (k + 1) * 128];
            c0 += g0_p1(v.x);
            c1 += g0_p1(v.y);
            c2 += g0_p1(v.z);
            c3 += g0_p1(v.w);
            if (k + 1 < 25) v = vn;
        }
    }
    ce_acc += (c0 + c1) + (c2 + c3);
    __syncthreads();   // s_tgt / s_vv complete before phase C

    // ---------------- Phase C: corrections ---------------------------------
    const float* rowbase = logits + ((size_t)b * NN + n0) * NC;

    // (1) invalid anchors: subtract whole-row t=0 contribution (rare path).
    //     Must reproduce phase B numerics: path chosen by anchor index.
    for (int a = warp; a < CH; a += 8) {
        if (s_vv[a] == 0.f) {
            const float* rp = rowbase + a * NC;
            float sub = 0.f;
            if (a < 64) { for (int c = lane; c < NC; c += 32) sub += g0_2m(rp[c]); }
            else        { for (int c = lane; c < NC; c += 32) sub += g0_p1(rp[c]); }
            #pragma unroll
            for (int o = 16; o; o >>= 1) sub += __shfl_xor_sync(0xffffffffu, sub, o);
            if (lane == 0) ce_acc -= sub;
        }
    }

    // (2) sparse t=1 cells: subtract phase-B's fl0 (matching path) and add
    //     exact-ish fl1 in lg2 units: (1/3)*(l - t)*r^2.
    #pragma unroll
    for (int kk = 0; kk < 4; ++kk) {
        int wq = tid + kk * 256;
        unsigned m = s_tgt[wq];
        if (m) {
            int a  = wq >> 3;
            int wi = wq & 7;
            float vf = s_vv[a];
            const float* rp = rowbase + a * NC + wi * 32;
            do {
                int bp = __ffs(m) - 1; m &= m - 1;
                float x = rp[bp];
                float t = x * LOG2E;
                float u = f_ex2(t);
                float s = 1.f + u;
                float r = f_rcp(s);
                float l = f_lg2(s);
                float fb = (a < 64) ? g0_2m(x) : g0_p1(x);
                ce_acc += vf * (0.33333333333f * (l - t) * r * r - fb);
            } while (m);
        }
    }

    // ---------------- Reduction + last-block finalize ----------------------
    #pragma unroll
    for (int o = 16; o; o >>= 1) {
        ce_acc  += __shfl_xor_sync(0xffffffffu, ce_acc,  o);
        seg_acc += __shfl_xor_sync(0xffffffffu, seg_acc, o);
        iou_acc += __shfl_xor_sync(0xffffffffu, iou_acc, o);
        cnt     += __shfl_xor_sync(0xffffffffu, cnt,     o);
    }
    if (lane == 0) {
        s_red[warp]      = ce_acc;
        s_red[8 + warp]  = seg_acc;
        s_red[16 + warp] = iou_acc;
        s_redc[warp]     = cnt;
    }
    __syncthreads();
    if (tid == 0) {
        double ce = 0.0, sg = 0.0, io = 0.0; int c = 0;
        #pragma unroll
        for (int w = 0; w < 8; ++w) {
            ce += (double)s_red[w];
            sg += (double)s_red[8 + w];
            io += (double)s_red[16 + w];
            c  += s_redc[w];
        }
        atomicAdd(&g_acc[0], ce);
        atomicAdd(&g_acc[1], sg);
        atomicAdd(&g_acc[2], io);
        atomicAdd(&g_cnt, (unsigned)c);
        __threadfence();
        unsigned t = atomicAdd(&g_done, 1u);
        if (t == TOTAL_BLOCKS - 1) {
            double np = (double)atomicAdd(&g_cnt, 0u);
            if (np < 1.0) np = 1.0;
            double a0 = atomicAdd(&g_acc[0], 0.0);
            double a1 = atomicAdd(&g_acc[1], 0.0);
            double a2 = atomicAdd(&g_acc[2], 0.0);
            out[0] = (float)(a0 * (0.75 * (double)LN2) / np);  // deferred 0.75*ln2
            out[1] = (float)(a1 / np);
            out[2] = (float)(a2 / np);
            g_acc[0] = 0.0; g_acc[1] = 0.0; g_acc[2] = 0.0;
            g_cnt = 0u; g_done = 0u;
        }
    }
}

extern "C" void kernel_launch(void* const* d_in, const int* in_sizes, int n_in,
                              void* d_out, int out_size) {
    const float*         logits = (const float*)d_in[0];
    const float*         psegs  = (const float*)d_in[1];
    const float*         grids  = (const float*)d_in[2];
    const float*         fps    = (const float*)d_in[3];
    const float*         gts    = (const float*)d_in[4];
    const int*           glab   = (const int*)d_in[5];
    const unsigned char* maskp  = (const unsigned char*)d_in[6];
    float* out = (float*)d_out;

    dim3 grid(NBX, NB);
    loss_fused<<<grid, 256>>>(logits, psegs, grids, fps, gts, glab, maskp, out);
    (void)in_sizes; (void)n_in; (void)out_size;
}

// round 16
// speedup vs baseline: 1.1765x; 1.1765x over previous
#include <cuda_runtime.h>

#define NB 4
#define NC 200
#define NG 32
#define NN 32256
#define CH 128                    // anchors per block
#define NBX (NN / CH)             // 252
#define TOTAL_BLOCKS (NB * NBX)   // 1008 -> single wave
#define QPT ((CH * 50) / 256)     // 25 quads per thread in phase B
#define LOG2E 1.4426950408889634f
#define LN2   0.69314718055994531f

__device__ double g_acc[3];
__device__ unsigned g_cnt;
__device__ unsigned g_done;

typedef unsigned long long ull;

__device__ __forceinline__ float f_ex2(float x){ float r; asm("ex2.approx.ftz.f32 %0,%1;" : "=f"(r) : "f"(x)); return r; }
__device__ __forceinline__ float f_lg2(float x){ float r; asm("lg2.approx.ftz.f32 %0,%1;" : "=f"(r) : "f"(x)); return r; }
__device__ __forceinline__ float f_rcp(float x){ float r; asm("rcp.approx.ftz.f32 %0,%1;" : "=f"(r) : "f"(x)); return r; }

// ---- packed f32x2 helpers (elementwise IEEE; register-pair operands) ----
__device__ __forceinline__ ull pk2(float a, float b){
    ull r; asm("mov.b64 %0, {%1, %2};" : "=l"(r) : "f"(a), "f"(b)); return r;
}
__device__ __forceinline__ void upk2(ull p, float& a, float& b){
    asm("mov.b64 {%0, %1}, %2;" : "=f"(a), "=f"(b) : "l"(p));
}
__device__ __forceinline__ ull f2mul(ull a, ull b){
    ull r; asm("mul.rn.f32x2 %0, %1, %2;" : "=l"(r) : "l"(a), "l"(b)); return r;
}
__device__ __forceinline__ ull f2add(ull a, ull b){
    ull r; asm("add.rn.f32x2 %0, %1, %2;" : "=l"(r) : "l"(a), "l"(b)); return r;
}
__device__ __forceinline__ ull f2fma(ull a, ull b, ull c){
    ull r; asm("fma.rn.f32x2 %0, %1, %2, %3;" : "=l"(r) : "l"(a), "l"(b), "l"(c)); return r;
}

#define ONE2  0x3F8000003F800000ULL
#define NONE2 0xBF800000BF800000ULL
#define L2E2  0x3FB8AA3B3FB8AA3BULL   // log2e (0x3FB8AA3B) in both lanes

// Scalar core mirroring the packed op order EXACTLY (phase C must reproduce
// phase B's per-element values): m = s*r0-1; p1 = m*m+1; q = p1-m; r = r0*q.
__device__ __forceinline__ float g0_2m(float x) {
    float t = x * LOG2E;
    float u = f_ex2(t);
    float s = 1.f + u;
    float l = f_lg2(s);
    float r0 = __int_as_float(0x7EF311C3 - __float_as_int(s));
    float m  = fmaf(s, r0, -1.f);
    float p1 = fmaf(m, m, 1.f);
    float q  = fmaf(m, -1.f, p1);
    float r  = r0 * q;
    float w = u * r;
    return l * w * w;
}

// Packed pair: two elements, 2 MUFU each, fp chain in f32x2 (half the issue).
__device__ __forceinline__ ull g0_pk(ull x01, ull accp) {
    ull t = f2mul(x01, L2E2);
    float t0, t1; upk2(t, t0, t1);
    float u0 = f_ex2(t0), u1 = f_ex2(t1);       // MUFU x2
    ull u = pk2(u0, u1);
    ull s = f2add(u, ONE2);
    float s0, s1; upk2(s, s0, s1);
    float l0 = f_lg2(s0), l1 = f_lg2(s1);       // MUFU x2
    float r00 = __int_as_float(0x7EF311C3 - __float_as_int(s0));
    float r01 = __int_as_float(0x7EF311C3 - __float_as_int(s1));
    ull r0 = pk2(r00, r01);
    ull m  = f2fma(s, r0, NONE2);               // s*r0 - 1
    ull p1 = f2fma(m, m, ONE2);                 // m^2 + 1
    ull q  = f2fma(m, NONE2, p1);               // 1 - m + m^2  (Halley factor)
    ull r  = f2mul(r0, q);
    ull w  = f2mul(u, r);
    ull ww = f2mul(w, w);
    ull l  = pk2(l0, l1);
    return f2fma(l, ww, accp);
}

__global__ void __launch_bounds__(256, 7)
loss_fused(const float* __restrict__ logits,        // [B,N,C]
           const float* __restrict__ psegs,         // [B,N,3]
           const float* __restrict__ grids,         // [B,N]
           const float* __restrict__ fps,           // [B]
           const float* __restrict__ gts,           // [B,G,2]
           const int*   __restrict__ glab,          // [B,G]
           const unsigned char* __restrict__ mask,  // [B,N]
           float* __restrict__ out)                 // [3]
{
    __shared__ unsigned s_tgt[CH * 8];   // 224-bit class-target mask per anchor
    __shared__ float    s_gv[CH], s_p1[CH], s_p2[CH], s_vv[CH];
    __shared__ float    s_red[3 * 8];
    __shared__ int      s_redc[8];

    const int tid  = threadIdx.x;
    const int lane = tid & 31;
    const int warp = tid >> 5;
    const int b    = blockIdx.y;
    const int n0   = blockIdx.x * CH;

    #pragma unroll
    for (int k = 0; k < 4; ++k) s_tgt[tid + k * 256] = 0u;
    if (tid < CH) {
        long long bn = (long long)b * NN + n0 + tid;
        s_gv[tid] = grids[bn];
        s_p1[tid] = psegs[bn * 3 + 1];
        s_p2[tid] = psegs[bn * 3 + 2];
        s_vv[tid] = mask[bn] ? 0.f : 1.f;
    }
    __syncthreads();

    // ---------------- Phase A: matching + seg/IoU + target masks ----------
    float2 seg  = ((const float2*)gts)[b * NG + lane];
    float s_g   = seg.x, e_g = seg.y;
    float len_g = e_g - s_g;
    int   lbl   = glab[b * NG + lane];
    float Cm    = 3.0f * fps[b] * 1.41421356237309515f;  // 3*fps*sqrt(2)

    int lvl = (n0 >= 16384) + (n0 >= 24576) + (n0 >= 28672) + (n0 >= 30720) + (n0 >= 31744);
    float lo = (lvl == 0) ? 0.f : Cm * (float)(1 << (lvl - 1));
    float hi = (lvl == 5) ? __int_as_float(0x7f800000) : Cm * (float)(1 << lvl);
    bool inb = (len_g >= lo) && (len_g < hi);

    float ce_acc = 0.f, seg_acc = 0.f, iou_acc = 0.f;
    int cnt = 0;

    #pragma unroll 4
    for (int i = 0; i < CH / 8; ++i) {   // 16 anchors per warp
        int a = warp * (CH / 8) + i;
        float gv = s_gv[a];
        bool pos = inb && (gv > s_g) && (gv < e_g);
        if (pos) {
            cnt++;
            float ps1 = s_p1[a], ps2 = s_p2[a];
            float d1 = ps1 - __logf(gv - s_g);
            float d2 = ps2 - __logf(e_g - gv);
            float a1 = fabsf(d1), a2 = fabsf(d2);
            seg_acc += (a1 < 1.f ? 0.5f * d1 * d1 : a1 - 0.5f)
                     + (a2 < 1.f ? 0.5f * d2 * d2 : a2 - 0.5f);
            float pls = gv - __expf(ps1);
            float ple = gv + __expf(ps2);
            float inter = fmaxf(fminf(ple, e_g) - fmaxf(pls, s_g), 0.f);
            float uni   = (ple - pls) + len_g - inter;
            iou_acc += 1.f - __fdividef(inter, uni);
            atomicOr(&s_tgt[a * 8 + (lbl >> 5)], 1u << (lbl & 31));
        }
    }
    // no barrier: phase B reads no phase-A shared state

    // ---------------- Phase B: packed-f32x2 2-MUFU focal stream ------------
    // Load ulonglong2 = two pre-packed f32 pairs per 16B (same LDG.128).
    const ulonglong2* basep =
        (const ulonglong2*)(logits + ((size_t)b * NN + n0) * NC);
    ull accA = 0, accB = 0;   // 0x0 == {+0.f, +0.f}
    ulonglong2 v = basep[tid];
    #pragma unroll
    for (int k = 0; k < QPT; ++k) {
        ulonglong2 vn;
        if (k + 1 < QPT) vn = basep[tid + (k + 1) * 256];
        accA = g0_pk(v.x, accA);
        accB = g0_pk(v.y, accB);
        if (k + 1 < QPT) v = vn;
    }
    {
        float a0, a1, b0, b1;
        upk2(accA, a0, a1);
        upk2(accB, b0, b1);
        ce_acc += (a0 + a1) + (b0 + b1);
    }
    __syncthreads();   // s_tgt / s_vv complete before phase C

    // ---------------- Phase C: corrections ---------------------------------
    const float* rowbase = logits + ((size_t)b * NN + n0) * NC;

    // (1) invalid anchors: subtract whole-row t=0 contribution (rare path).
    //     g0_2m mirrors the packed op order -> identical per-element values.
    for (int a = warp; a < CH; a += 8) {
        if (s_vv[a] == 0.f) {
            const float* rp = rowbase + a * NC;
            float sub = 0.f;
            for (int c = lane; c < NC; c += 32) sub += g0_2m(rp[c]);
            #pragma unroll
            for (int o = 16; o; o >>= 1) sub += __shfl_xor_sync(0xffffffffu, sub, o);
            if (lane == 0) ce_acc -= sub;
        }
    }

    // (2) sparse t=1 cells: add (fl1 - fl0) in lg2 units:
    //     (1/3)*(l - t)*r^2 - fl0(same-numerics)   (times valid)
    #pragma unroll
    for (int kk = 0; kk < 4; ++kk) {
        int wq = tid + kk * 256;
        unsigned m = s_tgt[wq];
        if (m) {
            int a  = wq >> 3;
            int wi = wq & 7;
            float vf = s_vv[a];
            const float* rp = rowbase + a * NC + wi * 32;
            do {
                int bp = __ffs(m) - 1; m &= m - 1;
                float x = rp[bp];
                float t = x * LOG2E;
                float u = f_ex2(t);
                float s = 1.f + u;
                float r = f_rcp(s);
                float l = f_lg2(s);
                float fb = g0_2m(x);
                ce_acc += vf * (0.33333333333f * (l - t) * r * r - fb);
            } while (m);
        }
    }

    // ---------------- Reduction + last-block finalize ----------------------
    #pragma unroll
    for (int o = 16; o; o >>= 1) {
        ce_acc  += __shfl_xor_sync(0xffffffffu, ce_acc,  o);
        seg_acc += __shfl_xor_sync(0xffffffffu, seg_acc, o);
        iou_acc += __shfl_xor_sync(0xffffffffu, iou_acc, o);
        cnt     += __shfl_xor_sync(0xffffffffu, cnt,     o);
    }
    if (lane == 0) {
        s_red[warp]      = ce_acc;
        s_red[8 + warp]  = seg_acc;
        s_red[16 + warp] = iou_acc;
        s_redc[warp]     = cnt;
    }
    __syncthreads();
    if (tid == 0) {
        double ce = 0.0, sg = 0.0, io = 0.0; int c = 0;
        #pragma unroll
        for (int w = 0; w < 8; ++w) {
            ce += (double)s_red[w];
            sg += (double)s_red[8 + w];
            io += (double)s_red[16 + w];
            c  += s_redc[w];
        }
        atomicAdd(&g_acc[0], ce);
        atomicAdd(&g_acc[1], sg);
        atomicAdd(&g_acc[2], io);
        atomicAdd(&g_cnt, (unsigned)c);
        __threadfence();
        unsigned t = atomicAdd(&g_done, 1u);
        if (t == TOTAL_BLOCKS - 1) {
            double np = (double)atomicAdd(&g_cnt, 0u);
            if (np < 1.0) np = 1.0;
            double a0 = atomicAdd(&g_acc[0], 0.0);
            double a1 = atomicAdd(&g_acc[1], 0.0);
            double a2 = atomicAdd(&g_acc[2], 0.0);
            out[0] = (float)(a0 * (0.75 * (double)LN2) / np);  // deferred 0.75*ln2
            out[1] = (float)(a1 / np);
            out[2] = (float)(a2 / np);
            g_acc[0] = 0.0; g_acc[1] = 0.0; g_acc[2] = 0.0;
            g_cnt = 0u; g_done = 0u;
        }
    }
}

extern "C" void kernel_launch(void* const* d_in, const int* in_sizes, int n_in,
                              void* d_out, int out_size) {
    const float*         logits = (const float*)d_in[0];
    const float*         psegs  = (const float*)d_in[1];
    const float*         grids  = (const float*)d_in[2];
    const float*         fps    = (const float*)d_in[3];
    const float*         gts    = (const float*)d_in[4];
    const int*           glab   = (const int*)d_in[5];
    const unsigned char* maskp  = (const unsigned char*)d_in[6];
    float* out = (float*)d_out;

    dim3 grid(NBX, NB);
    loss_fused<<<grid, 256>>>(logits, psegs, grids, fps, gts, glab, maskp, out);
    (void)in_sizes; (void)n_in; (void)out_size;
}